// round 12
// baseline (speedup 1.0000x reference)
#include <cuda_runtime.h>
#include <cstdint>

// ---------------------------------------------------------------------------
// out[b,co,y,x] = alpha[co] * sum_{ci,ky,kx} sign(x[..]) * sign(w[..])
// XNOR-popcount with CSA compression (R10-proven conv), vectorized pack.
// ---------------------------------------------------------------------------
#define NB   32
#define CIN  64
#define COUT 64
#define HH   160
#define WW   160
#define HW   (HH*WW)          // 25600
#define H2   162
#define W2   162
#define PADWORDS (NB*H2*W2)   // 839808

#define ZMAX 8192

// pack decomposition
#define NQUADS   (NB*HH*40)           // 204800 interior quad-threads
#define NBORDER  (NB*(2*W2 + 2*(H2-2)))  // 20608 border positions
#define PACK_THREADS (NQUADS + NBORDER)

__device__ unsigned long long g_packed[PADWORDS];
__device__ unsigned long long g_pw[COUT*9];
__device__ float              g_alpha[COUT];
__device__ float2             g_coeff[9*COUT];
__device__ int                g_zero_count;
__device__ int                g_zero_list[ZMAX];

// ---------------------------------------------------------------------------
// Kernel 1: weight prep. 64 blocks (co) x 64 threads (ci). Ballot bit-pack.
// ---------------------------------------------------------------------------
__global__ __launch_bounds__(64) void prep_kernel(const float* __restrict__ w)
{
    __shared__ unsigned bl[2][9];
    __shared__ float red[2];
    __shared__ float salpha;
    __shared__ int S[9];
    int co = blockIdx.x, ci = threadIdx.x;
    if (co == 0 && ci == 0) g_zero_count = 0;
    int lane = ci & 31, wrp = ci >> 5;
    float sum = 0.f;
#pragma unroll
    for (int t = 0; t < 9; t++) {
        float v = w[(co*CIN + ci)*9 + t];
        float vc = fminf(fmaxf(v, -1.f), 1.f);
        sum += fabsf(vc);
        unsigned m = __ballot_sync(0xFFFFFFFFu, !(__float_as_uint(vc) >> 31));
        if (lane == 0) bl[wrp][t] = m;
    }
#pragma unroll
    for (int o = 16; o > 0; o >>= 1) sum += __shfl_down_sync(0xFFFFFFFFu, sum, o);
    if (lane == 0) red[wrp] = sum;
    __syncthreads();
    if (ci == 0) {
        float a = (red[0] + red[1]) * (1.f/576.f);
        salpha = a;
        g_alpha[co] = a;
    }
    if (ci < 9) {
        unsigned long long bits =
            (unsigned long long)bl[0][ci] | ((unsigned long long)bl[1][ci] << 32);
        g_pw[co*9 + ci] = bits;
        S[ci] = 64 - 2*__popcll(bits);
    }
    __syncthreads();
    if (ci < 9) {
        int cy = ci / 3, cx = ci % 3;
        int corr = 0;
#pragma unroll
        for (int t = 0; t < 9; t++) {
            int ky = t/3, kx = t%3;
            bool oob = (cy==0&&ky==0)||(cy==2&&ky==2)||(cx==0&&kx==0)||(cx==2&&kx==2);
            if (oob) corr += S[t];
        }
        float2 c;
        c.x = salpha * (float)(576 - corr);
        c.y = -2.f * salpha;
        g_coeff[ci*COUT + co] = c;
    }
}

// ---------------------------------------------------------------------------
// Kernel 2: pack. Interior: thread = 4 adjacent pixels via float4 loads.
// Border: trailing threads zero the padded frame.
// ---------------------------------------------------------------------------
__global__ __launch_bounds__(256) void pack_kernel(const float* __restrict__ x)
{
    int id = blockIdx.x * 256 + threadIdx.x;

    if (id < NQUADS) {
        int b  = id / (HH*40);
        int r  = id % (HH*40);
        int y  = r / 40;
        int x0 = (r % 40) * 4;

        const float* px = x + (long long)b*CIN*HW + y*WW + x0;
        unsigned lo0=0, lo1=0, lo2=0, lo3=0, hi0=0, hi1=0, hi2=0, hi3=0;

#pragma unroll 8
        for (int ci = 0; ci < CIN; ci++) {
            float4 v = *(const float4*)(px + (long long)ci*HW);
            unsigned u0 = __float_as_uint(v.x), u1 = __float_as_uint(v.y);
            unsigned u2 = __float_as_uint(v.z), u3 = __float_as_uint(v.w);
            unsigned b0 = (u0 >> 31) ^ 1u, b1 = (u1 >> 31) ^ 1u;
            unsigned b2 = (u2 >> 31) ^ 1u, b3 = (u3 >> 31) ^ 1u;
            if (ci < 32) {
                lo0 |= b0 << ci; lo1 |= b1 << ci; lo2 |= b2 << ci; lo3 |= b3 << ci;
            } else {
                hi0 |= b0 << (ci-32); hi1 |= b1 << (ci-32);
                hi2 |= b2 << (ci-32); hi3 |= b3 << (ci-32);
            }
            // exact-zero fixup recording (rare)
            if ((u0 << 1) == 0u) {
                int s = atomicAdd(&g_zero_count, 1);
                if (s < ZMAX) g_zero_list[s] = (b<<23)|(ci<<17)|(y<<9)|((x0+0)<<1)|(int)b0;
            }
            if ((u1 << 1) == 0u) {
                int s = atomicAdd(&g_zero_count, 1);
                if (s < ZMAX) g_zero_list[s] = (b<<23)|(ci<<17)|(y<<9)|((x0+1)<<1)|(int)b1;
            }
            if ((u2 << 1) == 0u) {
                int s = atomicAdd(&g_zero_count, 1);
                if (s < ZMAX) g_zero_list[s] = (b<<23)|(ci<<17)|(y<<9)|((x0+2)<<1)|(int)b2;
            }
            if ((u3 << 1) == 0u) {
                int s = atomicAdd(&g_zero_count, 1);
                if (s < ZMAX) g_zero_list[s] = (b<<23)|(ci<<17)|(y<<9)|((x0+3)<<1)|(int)b3;
            }
        }
        unsigned long long* dst = g_packed + ((long long)b*H2 + (y+1))*W2 + (x0+1);
        dst[0] = (unsigned long long)lo0 | ((unsigned long long)hi0 << 32);
        dst[1] = (unsigned long long)lo1 | ((unsigned long long)hi1 << 32);
        dst[2] = (unsigned long long)lo2 | ((unsigned long long)hi2 << 32);
        dst[3] = (unsigned long long)lo3 | ((unsigned long long)hi3 << 32);
        return;
    }

    int id2 = id - NQUADS;
    if (id2 >= NBORDER) return;
    int perb = 2*W2 + 2*(H2-2);          // 644
    int b = id2 / perb;
    int p = id2 % perb;
    int y2, x2;
    if (p < W2)              { y2 = 0;        x2 = p; }
    else if (p < 2*W2)       { y2 = H2-1;     x2 = p - W2; }
    else if (p < 2*W2 + (H2-2)) { y2 = 1 + (p - 2*W2);        x2 = 0; }
    else                     { y2 = 1 + (p - 2*W2 - (H2-2));  x2 = W2-1; }
    g_packed[((long long)b*H2 + y2)*W2 + x2] = 0ull;
}

// ---------------------------------------------------------------------------
// CSA helpers
// ---------------------------------------------------------------------------
__device__ __forceinline__ void FA(unsigned a, unsigned b, unsigned c,
                                   unsigned& s, unsigned& cy)
{
    s  = a ^ b ^ c;
    cy = (a & b) | (c & (a | b));
}

__device__ __forceinline__ int popc9(const unsigned* v)
{
    unsigned s0,c0,s1,c1,s2,c2,s3,c3,s4,c4;
    FA(v[0], v[1], v[2], s0, c0);
    FA(v[3], v[4], v[5], s1, c1);
    FA(v[6], v[7], v[8], s2, c2);
    FA(s0, s1, s2, s3, c3);
    FA(c0, c1, c2, s4, c4);
    return __popc(s3) + 2*(__popc(c3) + __popc(s4)) + 4*__popc(c4);
}

// ---------------------------------------------------------------------------
// Kernel 3: main conv (R10-proven). Thread = one output pixel; 64 co CSA.
// ---------------------------------------------------------------------------
__global__ __launch_bounds__(256, 2) void conv_kernel(float* __restrict__ out)
{
    __shared__ __align__(16) unsigned swv[COUT*20];  // [co][20]: (lo,hi) x 9 taps + pad
    __shared__ float2 scoef[9*COUT];

    int tid = threadIdx.x;
    for (int i = tid; i < COUT*9; i += 256) {
        int co = i / 9, t = i % 9;
        unsigned long long bword = g_pw[i];
        swv[co*20 + 2*t]     = (unsigned)bword;
        swv[co*20 + 2*t + 1] = (unsigned)(bword >> 32);
    }
    for (int i = tid; i < 9*COUT; i += 256) scoef[i] = g_coeff[i];
    __syncthreads();

    int pix = blockIdx.x * blockDim.x + threadIdx.x;   // 0 .. 819199
    int b = pix / HW;
    int r = pix % HW;
    int y = r / WW;
    int xx = r % WW;

    const uint2* pp = (const uint2*)g_packed + ((long long)b*H2 + y)*W2 + xx;
    unsigned xl[9], xh[9];
#pragma unroll
    for (int ky = 0; ky < 3; ky++)
#pragma unroll
        for (int kx = 0; kx < 3; kx++) {
            uint2 v = pp[ky*W2 + kx];
            xl[ky*3+kx] = v.x;
            xh[ky*3+kx] = v.y;
        }

    int cy = (y == 0) ? 0 : ((y == HH-1) ? 2 : 1);
    int cx = (xx == 0) ? 0 : ((xx == WW-1) ? 2 : 1);
    const float2* cf = scoef + (cy*3 + cx) * COUT;

    float* outp = out + ((long long)b*COUT)*HW + y*WW + xx;

#pragma unroll 4
    for (int co = 0; co < COUT; co++) {
        unsigned wv[20];
#pragma unroll
        for (int k = 0; k < 5; k++)
            ((uint4*)wv)[k] = ((const uint4*)(swv + co*20))[k];

        unsigned vl[9], vh[9];
#pragma unroll
        for (int t = 0; t < 9; t++) {
            vl[t] = xl[t] ^ wv[2*t];
            vh[t] = xh[t] ^ wv[2*t + 1];
        }
        int acc = popc9(vl) + popc9(vh);
        float2 c = cf[co];
        outp[(long long)co*HW] = fmaf(c.y, (float)acc, c.x);
    }
}

// ---------------------------------------------------------------------------
// Kernel 4: fixup for exact-zero activations (sign(0)=0).
// ---------------------------------------------------------------------------
__global__ void fixup_kernel(float* __restrict__ out)
{
    int cnt = g_zero_count;
    if (cnt > ZMAX) cnt = ZMAX;
    int total = cnt * COUT * 9;
    for (int i = blockIdx.x * blockDim.x + threadIdx.x; i < total;
         i += gridDim.x * blockDim.x) {
        int zi  = i / (COUT*9);
        int rem = i % (COUT*9);
        int co  = rem / 9;
        int t   = rem % 9;
        int e   = g_zero_list[zi];
        int b   = (e >> 23) & 31;
        int ci  = (e >> 17) & 63;
        int y   = (e >> 9)  & 255;
        int xx  = (e >> 1)  & 255;
        int ts  = e & 1;
        int ky = t / 3, kx = t % 3;
        int yo = y - ky + 1;
        int xo = xx - kx + 1;
        if (yo < 0 || yo >= HH || xo < 0 || xo >= WW) continue;
        int wbit = (int)((g_pw[co*9 + t] >> ci) & 1ull);
        float ws  = wbit ? 1.0f : -1.0f;
        float tsf = ts   ? 1.0f : -1.0f;
        atomicAdd(&out[(((long long)b*COUT + co)*HH + yo)*WW + xo],
                  -g_alpha[co] * ws * tsf);
    }
}

// ---------------------------------------------------------------------------
extern "C" void kernel_launch(void* const* d_in, const int* in_sizes, int n_in,
                              void* d_out, int out_size)
{
    const float* x = (const float*)d_in[0];   // [32,64,160,160]
    const float* w = (const float*)d_in[1];   // [64,64,3,3]
    float* out = (float*)d_out;               // [32,64,160,160]

    prep_kernel<<<64, 64>>>(w);

    int packBlocks = (PACK_THREADS + 255) / 256;
    pack_kernel<<<packBlocks, 256>>>(x);

    conv_kernel<<<(NB*HW)/256, 256>>>(out);

    fixup_kernel<<<64, 256>>>(out);
}

// round 13
// speedup vs baseline: 1.2238x; 1.2238x over previous
#include <cuda_runtime.h>
#include <cstdint>

// ---------------------------------------------------------------------------
// out[b,co,y,x] = alpha[co] * sum_{ci,ky,kx} sign(x[..]) * sign(w[..])
// XNOR-popcount, balanced CSA (F=9: alu 72 / popc 72 cyc per pixel-co),
// 2 pixels per thread in both pack and conv.
// ---------------------------------------------------------------------------
#define NB   32
#define CIN  64
#define COUT 64
#define HH   160
#define WW   160
#define HW   (HH*WW)          // 25600
#define H2   162
#define W2   162
#define PADWORDS (NB*H2*W2)   // 839808

#define ZMAX 8192

// pack decomposition: interior pairs + border positions
#define NPAIRS   (NB*HH*80)              // 409600
#define NBORDER  (NB*(2*W2 + 2*(H2-2)))  // 20608
#define PACK_THREADS (NPAIRS + NBORDER)

__device__ unsigned long long g_packed[PADWORDS];
__device__ unsigned long long g_pw[COUT*9];
__device__ float              g_alpha[COUT];
__device__ float2             g_coeff[9*COUT];
__device__ int                g_zero_count;
__device__ int                g_zero_list[ZMAX];

// ---------------------------------------------------------------------------
// Kernel 1: weight prep. 64 blocks (co) x 64 threads (ci). Ballot bit-pack.
// ---------------------------------------------------------------------------
__global__ __launch_bounds__(64) void prep_kernel(const float* __restrict__ w)
{
    __shared__ unsigned bl[2][9];
    __shared__ float red[2];
    __shared__ float salpha;
    __shared__ int S[9];
    int co = blockIdx.x, ci = threadIdx.x;
    if (co == 0 && ci == 0) g_zero_count = 0;
    int lane = ci & 31, wrp = ci >> 5;
    float sum = 0.f;
#pragma unroll
    for (int t = 0; t < 9; t++) {
        float v = w[(co*CIN + ci)*9 + t];
        float vc = fminf(fmaxf(v, -1.f), 1.f);
        sum += fabsf(vc);
        unsigned m = __ballot_sync(0xFFFFFFFFu, !(__float_as_uint(vc) >> 31));
        if (lane == 0) bl[wrp][t] = m;
    }
#pragma unroll
    for (int o = 16; o > 0; o >>= 1) sum += __shfl_down_sync(0xFFFFFFFFu, sum, o);
    if (lane == 0) red[wrp] = sum;
    __syncthreads();
    if (ci == 0) {
        float a = (red[0] + red[1]) * (1.f/576.f);
        salpha = a;
        g_alpha[co] = a;
    }
    if (ci < 9) {
        unsigned long long bits =
            (unsigned long long)bl[0][ci] | ((unsigned long long)bl[1][ci] << 32);
        g_pw[co*9 + ci] = bits;
        S[ci] = 64 - 2*__popcll(bits);
    }
    __syncthreads();
    if (ci < 9) {
        int cy = ci / 3, cx = ci % 3;
        int corr = 0;
#pragma unroll
        for (int t = 0; t < 9; t++) {
            int ky = t/3, kx = t%3;
            bool oob = (cy==0&&ky==0)||(cy==2&&ky==2)||(cx==0&&kx==0)||(cx==2&&kx==2);
            if (oob) corr += S[t];
        }
        float2 c;
        c.x = salpha * (float)(576 - corr);
        c.y = -2.f * salpha;
        g_coeff[ci*COUT + co] = c;
    }
}

// ---------------------------------------------------------------------------
// Kernel 2: pack. Interior: thread = 2 adjacent pixels via aligned float2
// loads (x0 even). Border: trailing threads zero the padded frame.
// ---------------------------------------------------------------------------
__global__ __launch_bounds__(256) void pack_kernel(const float* __restrict__ x)
{
    int id = blockIdx.x * 256 + threadIdx.x;

    if (id < NPAIRS) {
        int b  = id / (HH*80);
        int r  = id % (HH*80);
        int y  = r / 80;
        int x0 = (r % 80) * 2;

        const float* px = x + (long long)b*CIN*HW + y*WW + x0;
        unsigned lo0 = 0, lo1 = 0, hi0 = 0, hi1 = 0;

#pragma unroll 8
        for (int ci = 0; ci < 32; ci++) {
            float2 v = *(const float2*)(px + (long long)ci*HW);
            unsigned u0 = __float_as_uint(v.x), u1 = __float_as_uint(v.y);
            unsigned b0 = (u0 >> 31) ^ 1u, b1 = (u1 >> 31) ^ 1u;
            lo0 |= b0 << ci;
            lo1 |= b1 << ci;
            if ((u0 << 1) == 0u) {
                int s = atomicAdd(&g_zero_count, 1);
                if (s < ZMAX) g_zero_list[s] = (b<<23)|(ci<<17)|(y<<9)|(x0<<1)|(int)b0;
            }
            if ((u1 << 1) == 0u) {
                int s = atomicAdd(&g_zero_count, 1);
                if (s < ZMAX) g_zero_list[s] = (b<<23)|(ci<<17)|(y<<9)|((x0+1)<<1)|(int)b1;
            }
        }
#pragma unroll 8
        for (int ci = 32; ci < 64; ci++) {
            float2 v = *(const float2*)(px + (long long)ci*HW);
            unsigned u0 = __float_as_uint(v.x), u1 = __float_as_uint(v.y);
            unsigned b0 = (u0 >> 31) ^ 1u, b1 = (u1 >> 31) ^ 1u;
            hi0 |= b0 << (ci-32);
            hi1 |= b1 << (ci-32);
            if ((u0 << 1) == 0u) {
                int s = atomicAdd(&g_zero_count, 1);
                if (s < ZMAX) g_zero_list[s] = (b<<23)|(ci<<17)|(y<<9)|(x0<<1)|(int)b0;
            }
            if ((u1 << 1) == 0u) {
                int s = atomicAdd(&g_zero_count, 1);
                if (s < ZMAX) g_zero_list[s] = (b<<23)|(ci<<17)|(y<<9)|((x0+1)<<1)|(int)b1;
            }
        }
        unsigned long long* dst = g_packed + ((long long)b*H2 + (y+1))*W2 + (x0+1);
        dst[0] = (unsigned long long)lo0 | ((unsigned long long)hi0 << 32);
        dst[1] = (unsigned long long)lo1 | ((unsigned long long)hi1 << 32);
        return;
    }

    int id2 = id - NPAIRS;
    if (id2 >= NBORDER) return;
    int perb = 2*W2 + 2*(H2-2);          // 644
    int b = id2 / perb;
    int p = id2 % perb;
    int y2, x2;
    if (p < W2)                 { y2 = 0;                     x2 = p; }
    else if (p < 2*W2)          { y2 = H2-1;                  x2 = p - W2; }
    else if (p < 2*W2 + (H2-2)) { y2 = 1 + (p - 2*W2);        x2 = 0; }
    else                        { y2 = 1 + (p - 2*W2 - (H2-2)); x2 = W2-1; }
    g_packed[((long long)b*H2 + y2)*W2 + x2] = 0ull;
}

// ---------------------------------------------------------------------------
// CSA helpers: balanced F=9 split across the two 32-bit halves.
// ---------------------------------------------------------------------------
__device__ __forceinline__ void FA(unsigned a, unsigned b, unsigned c,
                                   unsigned& s, unsigned& cy)
{
    s  = a ^ b ^ c;
    cy = (a & b) | (c & (a | b));
}

// 5 FA, 4 POPC  (R10-proven)
__device__ __forceinline__ int popc9a(const unsigned* v)
{
    unsigned s0,c0,s1,c1,s2,c2,s3,c3,s4,c4;
    FA(v[0], v[1], v[2], s0, c0);
    FA(v[3], v[4], v[5], s1, c1);
    FA(v[6], v[7], v[8], s2, c2);
    FA(s0, s1, s2, s3, c3);
    FA(c0, c1, c2, s4, c4);
    return __popc(s3) + 2*(__popc(c3) + __popc(s4)) + 4*__popc(c4);
}

// 4 FA, 5 POPC
__device__ __forceinline__ int popc9b(const unsigned* v)
{
    unsigned s0,c0,s1,c1,s2,c2,s3,c3;
    FA(v[0], v[1], v[2], s0, c0);
    FA(v[3], v[4], v[5], s1, c1);
    FA(v[6], v[7], v[8], s2, c2);
    FA(s0, s1, s2, s3, c3);
    return __popc(s3) + 2*(__popc(c0) + __popc(c1) + __popc(c2) + __popc(c3));
}

// one pixel from the 3x4 tap window, columns [cb, cb+2]
__device__ __forceinline__ int pix_count(const unsigned xl[3][4], const unsigned xh[3][4],
                                         int cb, const unsigned* wv)
{
    unsigned vl[9], vh[9];
#pragma unroll
    for (int ky = 0; ky < 3; ky++)
#pragma unroll
        for (int kx = 0; kx < 3; kx++) {
            int t = ky*3 + kx;
            vl[t] = xl[ky][cb+kx] ^ wv[2*t];
            vh[t] = xh[ky][cb+kx] ^ wv[2*t+1];
        }
    return popc9a(vl) + popc9b(vh);
}

// ---------------------------------------------------------------------------
// Kernel 3: main conv. Thread = TWO adjacent output pixels; 64 co, CSA F=9.
// ---------------------------------------------------------------------------
__global__ __launch_bounds__(256, 2) void conv_kernel(float* __restrict__ out)
{
    __shared__ __align__(16) unsigned swv[COUT*20];  // [co][20]: (lo,hi) x 9 taps + pad
    __shared__ float2 scoef[9*COUT];

    int tid = threadIdx.x;
    for (int i = tid; i < COUT*9; i += 256) {
        int co = i / 9, t = i % 9;
        unsigned long long bword = g_pw[i];
        swv[co*20 + 2*t]     = (unsigned)bword;
        swv[co*20 + 2*t + 1] = (unsigned)(bword >> 32);
    }
    for (int i = tid; i < 9*COUT; i += 256) scoef[i] = g_coeff[i];
    __syncthreads();

    int thr = blockIdx.x * 256 + tid;        // 0 .. 409599
    int p   = thr * 2;
    int b   = p / HW;
    int r   = p % HW;
    int y   = r / WW;
    int x0  = r % WW;                        // even; pair (x0, x0+1) same row

    // 12 tap words: padded rows y..y+2, padded cols x0..x0+3
    const uint2* pp = (const uint2*)g_packed + ((long long)b*H2 + y)*W2 + x0;
    unsigned xl[3][4], xh[3][4];
#pragma unroll
    for (int ky = 0; ky < 3; ky++)
#pragma unroll
        for (int c = 0; c < 4; c++) {
            uint2 v = pp[ky*W2 + c];
            xl[ky][c] = v.x;
            xh[ky][c] = v.y;
        }

    int cy  = (y == 0) ? 0 : ((y == HH-1) ? 2 : 1);
    int cx0 = (x0 == 0) ? 0 : 1;             // x0 even -> never WW-1
    int cx1 = (x0+1 == WW-1) ? 2 : 1;        // x0+1 odd -> never 0
    const float2* cf0 = scoef + (cy*3 + cx0) * COUT;
    const float2* cf1 = scoef + (cy*3 + cx1) * COUT;

    float* outp = out + ((long long)b*COUT)*HW + y*WW + x0;

#pragma unroll 2
    for (int co = 0; co < COUT; co++) {
        unsigned wv[20];
#pragma unroll
        for (int k = 0; k < 5; k++)
            ((uint4*)wv)[k] = ((const uint4*)(swv + co*20))[k];

        int acc0 = pix_count(xl, xh, 0, wv);
        int acc1 = pix_count(xl, xh, 1, wv);
        float2 c0 = cf0[co], c1 = cf1[co];
        float2 st;
        st.x = fmaf(c0.y, (float)acc0, c0.x);
        st.y = fmaf(c1.y, (float)acc1, c1.x);
        *(float2*)(outp + (long long)co*HW) = st;
    }
}

// ---------------------------------------------------------------------------
// Kernel 4: fixup for exact-zero activations (sign(0)=0).
// ---------------------------------------------------------------------------
__global__ void fixup_kernel(float* __restrict__ out)
{
    int cnt = g_zero_count;
    if (cnt > ZMAX) cnt = ZMAX;
    int total = cnt * COUT * 9;
    for (int i = blockIdx.x * blockDim.x + threadIdx.x; i < total;
         i += gridDim.x * blockDim.x) {
        int zi  = i / (COUT*9);
        int rem = i % (COUT*9);
        int co  = rem / 9;
        int t   = rem % 9;
        int e   = g_zero_list[zi];
        int b   = (e >> 23) & 31;
        int ci  = (e >> 17) & 63;
        int y   = (e >> 9)  & 255;
        int xx  = (e >> 1)  & 255;
        int ts  = e & 1;
        int ky = t / 3, kx = t % 3;
        int yo = y - ky + 1;
        int xo = xx - kx + 1;
        if (yo < 0 || yo >= HH || xo < 0 || xo >= WW) continue;
        int wbit = (int)((g_pw[co*9 + t] >> ci) & 1ull);
        float ws  = wbit ? 1.0f : -1.0f;
        float tsf = ts   ? 1.0f : -1.0f;
        atomicAdd(&out[(((long long)b*COUT + co)*HH + yo)*WW + xo],
                  -g_alpha[co] * ws * tsf);
    }
}

// ---------------------------------------------------------------------------
extern "C" void kernel_launch(void* const* d_in, const int* in_sizes, int n_in,
                              void* d_out, int out_size)
{
    const float* x = (const float*)d_in[0];   // [32,64,160,160]
    const float* w = (const float*)d_in[1];   // [64,64,3,3]
    float* out = (float*)d_out;               // [32,64,160,160]

    prep_kernel<<<64, 64>>>(w);

    int packBlocks = (PACK_THREADS + 255) / 256;
    pack_kernel<<<packBlocks, 256>>>(x);

    conv_kernel<<<(NB*HW)/512, 256>>>(out);

    fixup_kernel<<<64, 256>>>(out);
}

// round 15
// speedup vs baseline: 1.4913x; 1.2186x over previous
#include <cuda_runtime.h>
#include <cstdint>

// ---------------------------------------------------------------------------
// out[b,co,y,x] = alpha[co] * sum_{ci,ky,kx} sign(x[..]) * sign(w[..])
// XNOR-popcount, 1 pixel/thread conv (R10-proven), balanced F=9 CSA:
// lo half 5FA/4POPC, hi half 4FA/5POPC -> alu 72 / popc 72 cyc per pixel-co.
// ---------------------------------------------------------------------------
#define NB   32
#define CIN  64
#define COUT 64
#define HH   160
#define WW   160
#define HW   (HH*WW)          // 25600
#define H2   162
#define W2   162
#define PADWORDS (NB*H2*W2)   // 839808

#define ZMAX 8192

__device__ unsigned long long g_packed[PADWORDS];
__device__ unsigned long long g_pw[COUT*9];
__device__ float              g_alpha[COUT];
__device__ float2             g_coeff[9*COUT];
__device__ int                g_zero_count;
__device__ int                g_zero_list[ZMAX];

// ---------------------------------------------------------------------------
// Kernel 1: weight prep. 64 blocks (co) x 64 threads (ci). Ballot bit-pack.
// ---------------------------------------------------------------------------
__global__ __launch_bounds__(64) void prep_kernel(const float* __restrict__ w)
{
    __shared__ unsigned bl[2][9];
    __shared__ float red[2];
    __shared__ float salpha;
    __shared__ int S[9];
    int co = blockIdx.x, ci = threadIdx.x;
    if (co == 0 && ci == 0) g_zero_count = 0;
    int lane = ci & 31, wrp = ci >> 5;
    float sum = 0.f;
#pragma unroll
    for (int t = 0; t < 9; t++) {
        float v = w[(co*CIN + ci)*9 + t];
        float vc = fminf(fmaxf(v, -1.f), 1.f);
        sum += fabsf(vc);
        unsigned m = __ballot_sync(0xFFFFFFFFu, !(__float_as_uint(vc) >> 31));
        if (lane == 0) bl[wrp][t] = m;
    }
#pragma unroll
    for (int o = 16; o > 0; o >>= 1) sum += __shfl_down_sync(0xFFFFFFFFu, sum, o);
    if (lane == 0) red[wrp] = sum;
    __syncthreads();
    if (ci == 0) {
        float a = (red[0] + red[1]) * (1.f/576.f);
        salpha = a;
        g_alpha[co] = a;
    }
    if (ci < 9) {
        unsigned long long bits =
            (unsigned long long)bl[0][ci] | ((unsigned long long)bl[1][ci] << 32);
        g_pw[co*9 + ci] = bits;
        S[ci] = 64 - 2*__popcll(bits);
    }
    __syncthreads();
    if (ci < 9) {
        int cy = ci / 3, cx = ci % 3;
        int corr = 0;
#pragma unroll
        for (int t = 0; t < 9; t++) {
            int ky = t/3, kx = t%3;
            bool oob = (cy==0&&ky==0)||(cy==2&&ky==2)||(cx==0&&kx==0)||(cx==2&&kx==2);
            if (oob) corr += S[t];
        }
        float2 c;
        c.x = salpha * (float)(576 - corr);
        c.y = -2.f * salpha;
        g_coeff[ci*COUT + co] = c;
    }
}

// ---------------------------------------------------------------------------
// Kernel 2: pack activation signs into padded u64 words; record exact zeros.
// (R10-proven version, untouched)
// ---------------------------------------------------------------------------
__global__ void pack_kernel(const float* __restrict__ x)
{
    int idx = blockIdx.x * blockDim.x + threadIdx.x;
    if (idx >= PADWORDS) return;
    int b  = idx / (H2*W2);
    int r  = idx % (H2*W2);
    int y2 = r / W2;
    int x2 = r % W2;
    if (y2 == 0 || y2 == H2-1 || x2 == 0 || x2 == W2-1) {
        g_packed[idx] = 0ull;
        return;
    }
    int y = y2 - 1, xx = x2 - 1;
    const float* px = x + (long long)b*CIN*HW + y*WW + xx;

    unsigned long long word = 0ull;
#pragma unroll 8
    for (int ci = 0; ci < CIN; ci++) {
        float v = px[(long long)ci*HW];
        unsigned u = __float_as_uint(v);
        unsigned treated = (u >> 31) ^ 1u;
        if (!(u >> 31)) word |= (1ull << ci);
        if (v == 0.0f) {
            int slot = atomicAdd(&g_zero_count, 1);
            if (slot < ZMAX)
                g_zero_list[slot] = (b<<23) | (ci<<17) | (y<<9) | (xx<<1) | (int)treated;
        }
    }
    g_packed[idx] = word;
}

// ---------------------------------------------------------------------------
// CSA helpers: balanced F=9 split across the two 32-bit halves.
// ---------------------------------------------------------------------------
__device__ __forceinline__ void FA(unsigned a, unsigned b, unsigned c,
                                   unsigned& s, unsigned& cy)
{
    s  = a ^ b ^ c;
    cy = (a & b) | (c & (a | b));
}

// 5 FA, 4 POPC (R10-proven)
__device__ __forceinline__ int popc9a(const unsigned* v)
{
    unsigned s0,c0,s1,c1,s2,c2,s3,c3,s4,c4;
    FA(v[0], v[1], v[2], s0, c0);
    FA(v[3], v[4], v[5], s1, c1);
    FA(v[6], v[7], v[8], s2, c2);
    FA(s0, s1, s2, s3, c3);
    FA(c0, c1, c2, s4, c4);
    return __popc(s3) + 2*(__popc(c3) + __popc(s4)) + 4*__popc(c4);
}

// 4 FA, 5 POPC
__device__ __forceinline__ int popc9b(const unsigned* v)
{
    unsigned s0,c0,s1,c1,s2,c2,s3,c3;
    FA(v[0], v[1], v[2], s0, c0);
    FA(v[3], v[4], v[5], s1, c1);
    FA(v[6], v[7], v[8], s2, c2);
    FA(s0, s1, s2, s3, c3);
    return __popc(s3) + 2*(__popc(c0) + __popc(c1) + __popc(c2) + __popc(c3));
}

// ---------------------------------------------------------------------------
// Kernel 3: main conv. Thread = one output pixel; loops 64 co with CSA popc.
// Identical to R10 except popc9b on the hi half (F=9 pipe balance).
// ---------------------------------------------------------------------------
__global__ __launch_bounds__(256, 2) void conv_kernel(float* __restrict__ out)
{
    __shared__ __align__(16) unsigned swv[COUT*20];  // [co][20]: (lo,hi) x 9 taps + pad
    __shared__ float2 scoef[9*COUT];

    int tid = threadIdx.x;
    for (int i = tid; i < COUT*9; i += 256) {
        int co = i / 9, t = i % 9;
        unsigned long long bword = g_pw[i];
        swv[co*20 + 2*t]     = (unsigned)bword;
        swv[co*20 + 2*t + 1] = (unsigned)(bword >> 32);
    }
    for (int i = tid; i < 9*COUT; i += 256) scoef[i] = g_coeff[i];
    __syncthreads();

    int pix = blockIdx.x * blockDim.x + threadIdx.x;   // 0 .. 819199
    int b = pix / HW;
    int r = pix % HW;
    int y = r / WW;
    int xx = r % WW;

    const uint2* pp = (const uint2*)g_packed + ((long long)b*H2 + y)*W2 + xx;
    unsigned xl[9], xh[9];
#pragma unroll
    for (int ky = 0; ky < 3; ky++)
#pragma unroll
        for (int kx = 0; kx < 3; kx++) {
            uint2 v = pp[ky*W2 + kx];
            xl[ky*3+kx] = v.x;
            xh[ky*3+kx] = v.y;
        }

    int cy = (y == 0) ? 0 : ((y == HH-1) ? 2 : 1);
    int cx = (xx == 0) ? 0 : ((xx == WW-1) ? 2 : 1);
    const float2* cf = scoef + (cy*3 + cx) * COUT;

    float* outp = out + ((long long)b*COUT)*HW + y*WW + xx;

#pragma unroll 4
    for (int co = 0; co < COUT; co++) {
        unsigned wv[20];
#pragma unroll
        for (int k = 0; k < 5; k++)
            ((uint4*)wv)[k] = ((const uint4*)(swv + co*20))[k];

        unsigned vl[9], vh[9];
#pragma unroll
        for (int t = 0; t < 9; t++) {
            vl[t] = xl[t] ^ wv[2*t];
            vh[t] = xh[t] ^ wv[2*t + 1];
        }
        int acc = popc9a(vl) + popc9b(vh);
        float2 c = cf[co];
        outp[(long long)co*HW] = fmaf(c.y, (float)acc, c.x);
    }
}

// ---------------------------------------------------------------------------
// Kernel 4: fixup for exact-zero activations (sign(0)=0).
// ---------------------------------------------------------------------------
__global__ void fixup_kernel(float* __restrict__ out)
{
    int cnt = g_zero_count;
    if (cnt > ZMAX) cnt = ZMAX;
    int total = cnt * COUT * 9;
    for (int i = blockIdx.x * blockDim.x + threadIdx.x; i < total;
         i += gridDim.x * blockDim.x) {
        int zi  = i / (COUT*9);
        int rem = i % (COUT*9);
        int co  = rem / 9;
        int t   = rem % 9;
        int e   = g_zero_list[zi];
        int b   = (e >> 23) & 31;
        int ci  = (e >> 17) & 63;
        int y   = (e >> 9)  & 255;
        int xx  = (e >> 1)  & 255;
        int ts  = e & 1;
        int ky = t / 3, kx = t % 3;
        int yo = y - ky + 1;
        int xo = xx - kx + 1;
        if (yo < 0 || yo >= HH || xo < 0 || xo >= WW) continue;
        int wbit = (int)((g_pw[co*9 + t] >> ci) & 1ull);
        float ws  = wbit ? 1.0f : -1.0f;
        float tsf = ts   ? 1.0f : -1.0f;
        atomicAdd(&out[(((long long)b*COUT + co)*HH + yo)*WW + xo],
                  -g_alpha[co] * ws * tsf);
    }
}

// ---------------------------------------------------------------------------
extern "C" void kernel_launch(void* const* d_in, const int* in_sizes, int n_in,
                              void* d_out, int out_size)
{
    const float* x = (const float*)d_in[0];   // [32,64,160,160]
    const float* w = (const float*)d_in[1];   // [64,64,3,3]
    float* out = (float*)d_out;               // [32,64,160,160]

    prep_kernel<<<64, 64>>>(w);

    int packBlocks = (PADWORDS + 255) / 256;
    pack_kernel<<<packBlocks, 256>>>(x);

    conv_kernel<<<(NB*HW)/256, 256>>>(out);

    fixup_kernel<<<64, 256>>>(out);
}

// round 16
// speedup vs baseline: 1.5416x; 1.0337x over previous
#include <cuda_runtime.h>
#include <cstdint>

// ---------------------------------------------------------------------------
// out[b,co,y,x] = alpha[co] * sum_{ci,ky,kx} sign(x[..]) * sign(w[..])
// XNOR-popcount with CSA (R10-frozen conv). Pack: 4 pixels/thread, float4,
// branch-free hot loop, rare-path exact-zero recording.
// ---------------------------------------------------------------------------
#define NB   32
#define CIN  64
#define COUT 64
#define HH   160
#define WW   160
#define HW   (HH*WW)          // 25600
#define H2   162
#define W2   162
#define PADWORDS (NB*H2*W2)   // 839808

#define ZMAX 8192

// pack decomposition: interior quads + border positions
#define NQUADS   (NB*HH*40)              // 204800
#define NBORDER  (NB*(2*W2 + 2*(H2-2)))  // 20608
#define PACK_THREADS (NQUADS + NBORDER)

__device__ unsigned long long g_packed[PADWORDS];
__device__ unsigned long long g_pw[COUT*9];
__device__ float              g_alpha[COUT];
__device__ float2             g_coeff[9*COUT];
__device__ int                g_zero_count;
__device__ int                g_zero_list[ZMAX];

// ---------------------------------------------------------------------------
// Kernel 1: weight prep. 64 blocks (co) x 64 threads (ci). Ballot bit-pack.
// ---------------------------------------------------------------------------
__global__ __launch_bounds__(64) void prep_kernel(const float* __restrict__ w)
{
    __shared__ unsigned bl[2][9];
    __shared__ float red[2];
    __shared__ float salpha;
    __shared__ int S[9];
    int co = blockIdx.x, ci = threadIdx.x;
    if (co == 0 && ci == 0) g_zero_count = 0;
    int lane = ci & 31, wrp = ci >> 5;
    float sum = 0.f;
#pragma unroll
    for (int t = 0; t < 9; t++) {
        float v = w[(co*CIN + ci)*9 + t];
        float vc = fminf(fmaxf(v, -1.f), 1.f);
        sum += fabsf(vc);
        unsigned m = __ballot_sync(0xFFFFFFFFu, !(__float_as_uint(vc) >> 31));
        if (lane == 0) bl[wrp][t] = m;
    }
#pragma unroll
    for (int o = 16; o > 0; o >>= 1) sum += __shfl_down_sync(0xFFFFFFFFu, sum, o);
    if (lane == 0) red[wrp] = sum;
    __syncthreads();
    if (ci == 0) {
        float a = (red[0] + red[1]) * (1.f/576.f);
        salpha = a;
        g_alpha[co] = a;
    }
    if (ci < 9) {
        unsigned long long bits =
            (unsigned long long)bl[0][ci] | ((unsigned long long)bl[1][ci] << 32);
        g_pw[co*9 + ci] = bits;
        S[ci] = 64 - 2*__popcll(bits);
    }
    __syncthreads();
    if (ci < 9) {
        int cy = ci / 3, cx = ci % 3;
        int corr = 0;
#pragma unroll
        for (int t = 0; t < 9; t++) {
            int ky = t/3, kx = t%3;
            bool oob = (cy==0&&ky==0)||(cy==2&&ky==2)||(cx==0&&kx==0)||(cx==2&&kx==2);
            if (oob) corr += S[t];
        }
        float2 c;
        c.x = salpha * (float)(576 - corr);
        c.y = -2.f * salpha;
        g_coeff[ci*COUT + co] = c;
    }
}

// ---------------------------------------------------------------------------
// Kernel 2: pack. Interior: thread = 4 adjacent pixels via float4 loads,
// branch-free; exact-zero recording in a rare second pass.
// Border: trailing threads zero the padded frame.
// ---------------------------------------------------------------------------
__global__ __launch_bounds__(256) void pack_kernel(const float* __restrict__ x)
{
    int id = blockIdx.x * 256 + threadIdx.x;

    if (id < NQUADS) {
        int b  = id / (HH*40);
        int r  = id % (HH*40);
        int y  = r / 40;
        int x0 = (r % 40) * 4;

        const float* px = x + (long long)b*CIN*HW + y*WW + x0;
        unsigned lo0=0, lo1=0, lo2=0, lo3=0, hi0=0, hi1=0, hi2=0, hi3=0;
        bool zany = false;

#pragma unroll 8
        for (int ci = 0; ci < 32; ci++) {
            float4 v = *(const float4*)(px + (long long)ci*HW);
            unsigned u0 = __float_as_uint(v.x), u1 = __float_as_uint(v.y);
            unsigned u2 = __float_as_uint(v.z), u3 = __float_as_uint(v.w);
            lo0 |= ((~u0) >> 31) << ci;
            lo1 |= ((~u1) >> 31) << ci;
            lo2 |= ((~u2) >> 31) << ci;
            lo3 |= ((~u3) >> 31) << ci;
            zany |= ((u0 << 1) == 0u) | ((u1 << 1) == 0u)
                  | ((u2 << 1) == 0u) | ((u3 << 1) == 0u);
        }
#pragma unroll 8
        for (int ci = 32; ci < 64; ci++) {
            float4 v = *(const float4*)(px + (long long)ci*HW);
            unsigned u0 = __float_as_uint(v.x), u1 = __float_as_uint(v.y);
            unsigned u2 = __float_as_uint(v.z), u3 = __float_as_uint(v.w);
            hi0 |= ((~u0) >> 31) << (ci-32);
            hi1 |= ((~u1) >> 31) << (ci-32);
            hi2 |= ((~u2) >> 31) << (ci-32);
            hi3 |= ((~u3) >> 31) << (ci-32);
            zany |= ((u0 << 1) == 0u) | ((u1 << 1) == 0u)
                  | ((u2 << 1) == 0u) | ((u3 << 1) == 0u);
        }

        unsigned long long* dst = g_packed + ((long long)b*H2 + (y+1))*W2 + (x0+1);
        dst[0] = (unsigned long long)lo0 | ((unsigned long long)hi0 << 32);
        dst[1] = (unsigned long long)lo1 | ((unsigned long long)hi1 << 32);
        dst[2] = (unsigned long long)lo2 | ((unsigned long long)hi2 << 32);
        dst[3] = (unsigned long long)lo3 | ((unsigned long long)hi3 << 32);

        // rare path: some element was exactly 0.0f -> record for fixup
        if (zany) {
            for (int ci = 0; ci < CIN; ci++) {
#pragma unroll
                for (int j = 0; j < 4; j++) {
                    unsigned u = __float_as_uint(px[(long long)ci*HW + j]);
                    if ((u << 1) == 0u) {
                        unsigned treated = (u >> 31) ^ 1u;
                        int s = atomicAdd(&g_zero_count, 1);
                        if (s < ZMAX)
                            g_zero_list[s] = (b<<23)|(ci<<17)|(y<<9)|((x0+j)<<1)|(int)treated;
                    }
                }
            }
        }
        return;
    }

    int id2 = id - NQUADS;
    if (id2 >= NBORDER) return;
    int perb = 2*W2 + 2*(H2-2);          // 644
    int b = id2 / perb;
    int p = id2 % perb;
    int y2, x2;
    if (p < W2)                 { y2 = 0;                       x2 = p; }
    else if (p < 2*W2)          { y2 = H2-1;                    x2 = p - W2; }
    else if (p < 2*W2 + (H2-2)) { y2 = 1 + (p - 2*W2);          x2 = 0; }
    else                        { y2 = 1 + (p - 2*W2 - (H2-2)); x2 = W2-1; }
    g_packed[((long long)b*H2 + y2)*W2 + x2] = 0ull;
}

// ---------------------------------------------------------------------------
// CSA helpers (R10-frozen)
// ---------------------------------------------------------------------------
__device__ __forceinline__ void FA(unsigned a, unsigned b, unsigned c,
                                   unsigned& s, unsigned& cy)
{
    s  = a ^ b ^ c;
    cy = (a & b) | (c & (a | b));
}

__device__ __forceinline__ int popc9(const unsigned* v)
{
    unsigned s0,c0,s1,c1,s2,c2,s3,c3,s4,c4;
    FA(v[0], v[1], v[2], s0, c0);
    FA(v[3], v[4], v[5], s1, c1);
    FA(v[6], v[7], v[8], s2, c2);
    FA(s0, s1, s2, s3, c3);
    FA(c0, c1, c2, s4, c4);
    return __popc(s3) + 2*(__popc(c3) + __popc(s4)) + 4*__popc(c4);
}

// ---------------------------------------------------------------------------
// Kernel 3: main conv (R10-frozen). Thread = one output pixel; 64 co CSA.
// ---------------------------------------------------------------------------
__global__ __launch_bounds__(256, 2) void conv_kernel(float* __restrict__ out)
{
    __shared__ __align__(16) unsigned swv[COUT*20];  // [co][20]: (lo,hi) x 9 taps + pad
    __shared__ float2 scoef[9*COUT];

    int tid = threadIdx.x;
    for (int i = tid; i < COUT*9; i += 256) {
        int co = i / 9, t = i % 9;
        unsigned long long bword = g_pw[i];
        swv[co*20 + 2*t]     = (unsigned)bword;
        swv[co*20 + 2*t + 1] = (unsigned)(bword >> 32);
    }
    for (int i = tid; i < 9*COUT; i += 256) scoef[i] = g_coeff[i];
    __syncthreads();

    int pix = blockIdx.x * blockDim.x + threadIdx.x;   // 0 .. 819199
    int b = pix / HW;
    int r = pix % HW;
    int y = r / WW;
    int xx = r % WW;

    const uint2* pp = (const uint2*)g_packed + ((long long)b*H2 + y)*W2 + xx;
    unsigned xl[9], xh[9];
#pragma unroll
    for (int ky = 0; ky < 3; ky++)
#pragma unroll
        for (int kx = 0; kx < 3; kx++) {
            uint2 v = pp[ky*W2 + kx];
            xl[ky*3+kx] = v.x;
            xh[ky*3+kx] = v.y;
        }

    int cy = (y == 0) ? 0 : ((y == HH-1) ? 2 : 1);
    int cx = (xx == 0) ? 0 : ((xx == WW-1) ? 2 : 1);
    const float2* cf = scoef + (cy*3 + cx) * COUT;

    float* outp = out + ((long long)b*COUT)*HW + y*WW + xx;

#pragma unroll 4
    for (int co = 0; co < COUT; co++) {
        unsigned wv[20];
#pragma unroll
        for (int k = 0; k < 5; k++)
            ((uint4*)wv)[k] = ((const uint4*)(swv + co*20))[k];

        unsigned vl[9], vh[9];
#pragma unroll
        for (int t = 0; t < 9; t++) {
            vl[t] = xl[t] ^ wv[2*t];
            vh[t] = xh[t] ^ wv[2*t + 1];
        }
        int acc = popc9(vl) + popc9(vh);
        float2 c = cf[co];
        outp[(long long)co*HW] = fmaf(c.y, (float)acc, c.x);
    }
}

// ---------------------------------------------------------------------------
// Kernel 4: fixup for exact-zero activations (sign(0)=0).
// ---------------------------------------------------------------------------
__global__ void fixup_kernel(float* __restrict__ out)
{
    int cnt = g_zero_count;
    if (cnt > ZMAX) cnt = ZMAX;
    int total = cnt * COUT * 9;
    for (int i = blockIdx.x * blockDim.x + threadIdx.x; i < total;
         i += gridDim.x * blockDim.x) {
        int zi  = i / (COUT*9);
        int rem = i % (COUT*9);
        int co  = rem / 9;
        int t   = rem % 9;
        int e   = g_zero_list[zi];
        int b   = (e >> 23) & 31;
        int ci  = (e >> 17) & 63;
        int y   = (e >> 9)  & 255;
        int xx  = (e >> 1)  & 255;
        int ts  = e & 1;
        int ky = t / 3, kx = t % 3;
        int yo = y - ky + 1;
        int xo = xx - kx + 1;
        if (yo < 0 || yo >= HH || xo < 0 || xo >= WW) continue;
        int wbit = (int)((g_pw[co*9 + t] >> ci) & 1ull);
        float ws  = wbit ? 1.0f : -1.0f;
        float tsf = ts   ? 1.0f : -1.0f;
        atomicAdd(&out[(((long long)b*COUT + co)*HH + yo)*WW + xo],
                  -g_alpha[co] * ws * tsf);
    }
}

// ---------------------------------------------------------------------------
extern "C" void kernel_launch(void* const* d_in, const int* in_sizes, int n_in,
                              void* d_out, int out_size)
{
    const float* x = (const float*)d_in[0];   // [32,64,160,160]
    const float* w = (const float*)d_in[1];   // [64,64,3,3]
    float* out = (float*)d_out;               // [32,64,160,160]

    prep_kernel<<<64, 64>>>(w);

    int packBlocks = (PACK_THREADS + 255) / 256;
    pack_kernel<<<packBlocks, 256>>>(x);

    conv_kernel<<<(NB*HW)/256, 256>>>(out);

    fixup_kernel<<<64, 256>>>(out);
}